// round 1
// baseline (speedup 1.0000x reference)
#include <cuda_runtime.h>
#include <cuda_bf16.h>
#include <math.h>

// Problem constants
#define DIM   1536
#define NH    12
#define HD    128
#define SEQ   3744          // 3*26*48
#define GH    26
#define GW    48
#define C2    64            // HD/2
#define SP0   22            // split boundaries in C2
#define SP1   43
#define EPSV  1e-6f
#define SCALE 0.08838834764831843f   // HD^-0.5

// Scratch (static device arrays: allocation-free)
__device__ float g_q[SEQ * DIM];
__device__ float g_k[SEQ * DIM];
__device__ float g_v[SEQ * DIM];
__device__ float g_attn[SEQ * DIM];

// ---------------------------------------------------------------------------
// GEMM: C[M][1536] = A[M][1536] @ W[1536][1536]^T + bias
// (both A and W are row-major with K contiguous)
// BM=64, BN=64, BK=16, 256 threads, 4x4 microtile per thread.
// ---------------------------------------------------------------------------
__global__ __launch_bounds__(256) void gemm_bias_kernel(
    const float* __restrict__ A, const float* __restrict__ W,
    const float* __restrict__ bias, float* __restrict__ C, int M)
{
    __shared__ float As[16][68];
    __shared__ float Bs[16][68];

    const int tid  = threadIdx.x;
    const int tx   = tid & 15;
    const int ty   = tid >> 4;
    const int row0 = blockIdx.y * 64;
    const int col0 = blockIdx.x * 64;
    const int lr   = tid >> 2;        // 0..63
    const int lc   = (tid & 3) * 4;   // 0,4,8,12

    float acc[4][4] = {};

    for (int kt = 0; kt < DIM; kt += 16) {
        // Load A tile (64 x 16), transposed into As[k][m]
        float4 av = make_float4(0.f, 0.f, 0.f, 0.f);
        int ar = row0 + lr;
        if (ar < M) av = *(const float4*)&A[(size_t)ar * DIM + kt + lc];
        As[lc + 0][lr] = av.x;
        As[lc + 1][lr] = av.y;
        As[lc + 2][lr] = av.z;
        As[lc + 3][lr] = av.w;

        // Load W tile (64 x 16), transposed into Bs[k][n]
        float4 wv = *(const float4*)&W[(size_t)(col0 + lr) * DIM + kt + lc];
        Bs[lc + 0][lr] = wv.x;
        Bs[lc + 1][lr] = wv.y;
        Bs[lc + 2][lr] = wv.z;
        Bs[lc + 3][lr] = wv.w;

        __syncthreads();

        #pragma unroll
        for (int k = 0; k < 16; ++k) {
            float4 a4 = *(const float4*)&As[k][ty * 4];
            float4 b4 = *(const float4*)&Bs[k][tx * 4];
            float a[4] = {a4.x, a4.y, a4.z, a4.w};
            float b[4] = {b4.x, b4.y, b4.z, b4.w};
            #pragma unroll
            for (int i = 0; i < 4; ++i)
                #pragma unroll
                for (int j = 0; j < 4; ++j)
                    acc[i][j] += a[i] * b[j];
        }
        __syncthreads();
    }

    #pragma unroll
    for (int i = 0; i < 4; ++i) {
        int r = row0 + ty * 4 + i;
        if (r < M) {
            #pragma unroll
            for (int j = 0; j < 4; ++j) {
                int c = col0 + tx * 4 + j;
                C[(size_t)r * DIM + c] = acc[i][j] + bias[c];
            }
        }
    }
}

// ---------------------------------------------------------------------------
// Fused RMSNorm (over full DIM) + gamma + RoPE (3D grid angles), in place.
// One block per sequence position.
// ---------------------------------------------------------------------------
__global__ __launch_bounds__(256) void rmsnorm_rope_kernel(
    float* __restrict__ t, const float* __restrict__ g,
    const float* __restrict__ freqs)
{
    __shared__ float row[DIM];
    __shared__ float red[256];

    const int s   = blockIdx.x;
    const int tid = threadIdx.x;
    float* rp = t + (size_t)s * DIM;

    float ss = 0.f;
    for (int i = tid; i < DIM; i += 256) {
        float v = rp[i];
        row[i] = v;
        ss += v * v;
    }
    red[tid] = ss;
    __syncthreads();
    for (int o = 128; o > 0; o >>= 1) {
        if (tid < o) red[tid] += red[tid + o];
        __syncthreads();
    }
    const float scale = rsqrtf(red[0] / (float)DIM + EPSV);

    const int f   = s / (GH * GW);
    const int rem = s % (GH * GW);
    const int hh  = rem / GW;
    const int ww  = rem % GW;

    for (int p = tid; p < NH * C2; p += 256) {
        const int head = p >> 6;
        const int j    = p & 63;
        const int pos  = (j < SP0) ? f : ((j < SP1) ? hh : ww);
        const float ang = freqs[pos * C2 + j];
        float si, co;
        sincosf(ang, &si, &co);
        const int i0 = head * HD + 2 * j;
        const float xr = row[i0]     * scale * g[i0];
        const float xi = row[i0 + 1] * scale * g[i0 + 1];
        rp[i0]     = xr * co - xi * si;
        rp[i0 + 1] = xr * si + xi * co;
    }
}

// ---------------------------------------------------------------------------
// Flash attention (fp32): BQ=64 queries x one head per block, BK=32 key tiles,
// online softmax, O accumulator in registers.
// ---------------------------------------------------------------------------
#define QPAD 132   // 128 + 4 (keeps float4 alignment: 132*4 = 528 bytes)
#define PPAD 33

__global__ __launch_bounds__(256) void attn_kernel(
    const float* __restrict__ Q, const float* __restrict__ K,
    const float* __restrict__ V, const int* __restrict__ seq_lens,
    float* __restrict__ O)
{
    extern __shared__ float sm[];
    float* Qs   = sm;                    // 64 * 132
    float* Ks   = Qs + 64 * QPAD;        // 32 * 132
    float* Vs   = Ks + 32 * QPAD;        // 32 * 132
    float* Ps   = Vs + 32 * QPAD;        // 64 * 33
    float* mrow = Ps + 64 * PPAD;        // 64
    float* lrow = mrow + 64;             // 64
    float* frow = lrow + 64;             // 64

    const int tid    = threadIdx.x;
    const int head   = blockIdx.y;
    const int q0     = blockIdx.x * 64;
    const int seqlen = seq_lens[0];
    const int tx     = tid & 15;   // 0..15
    const int ty     = tid >> 4;   // 0..15

    // Load Q tile (rows q0..q0+63 of this head)
    for (int i = tid; i < 64 * HD; i += 256) {
        int r = i >> 7, d = i & 127;
        float v = 0.f;
        if (q0 + r < SEQ) v = Q[(size_t)(q0 + r) * DIM + head * HD + d];
        Qs[r * QPAD + d] = v;
    }
    if (tid < 64) { mrow[tid] = -1e30f; lrow[tid] = 0.f; }

    float acc[4][8] = {};   // O fragment: rows ty*4..+3, cols tx*8..+7
    __syncthreads();

    for (int k0 = 0; k0 < seqlen; k0 += 32) {
        // Load K,V tiles (32 x 128)
        for (int i = tid; i < 32 * HD; i += 256) {
            int r = i >> 7, d = i & 127;
            size_t gi = (size_t)(k0 + r) * DIM + head * HD + d;
            Ks[r * QPAD + d] = K[gi];
            Vs[r * QPAD + d] = V[gi];
        }
        __syncthreads();

        // S tile = Q @ K^T : thread computes rows ty*4..+3, kcols tx*2..+1
        float s4[4][2] = {};
        #pragma unroll 8
        for (int d = 0; d < HD; d += 4) {
            float4 qv[4], kv[2];
            #pragma unroll
            for (int i = 0; i < 4; ++i)
                qv[i] = *(const float4*)&Qs[(ty * 4 + i) * QPAD + d];
            #pragma unroll
            for (int j = 0; j < 2; ++j)
                kv[j] = *(const float4*)&Ks[(tx * 2 + j) * QPAD + d];
            #pragma unroll
            for (int i = 0; i < 4; ++i)
                #pragma unroll
                for (int j = 0; j < 2; ++j) {
                    s4[i][j] += qv[i].x * kv[j].x + qv[i].y * kv[j].y
                              + qv[i].z * kv[j].z + qv[i].w * kv[j].w;
                }
        }
        #pragma unroll
        for (int i = 0; i < 4; ++i)
            #pragma unroll
            for (int j = 0; j < 2; ++j) {
                int kk = tx * 2 + j;
                float v = s4[i][j] * SCALE;
                if (k0 + kk >= seqlen) v = -1e9f;
                Ps[(ty * 4 + i) * PPAD + kk] = v;
            }
        __syncthreads();

        // Online softmax: one thread per query row
        if (tid < 64) {
            const int r = tid;
            float mold = mrow[r], mx = mold;
            #pragma unroll
            for (int j = 0; j < 32; ++j) mx = fmaxf(mx, Ps[r * PPAD + j]);
            float fac = expf(mold - mx);
            float sum = 0.f;
            #pragma unroll
            for (int j = 0; j < 32; ++j) {
                float p = expf(Ps[r * PPAD + j] - mx);
                Ps[r * PPAD + j] = p;
                sum += p;
            }
            mrow[r] = mx;
            frow[r] = fac;
            lrow[r] = lrow[r] * fac + sum;
        }
        __syncthreads();

        // Rescale O acc, then O += P @ V
        float fr[4];
        #pragma unroll
        for (int i = 0; i < 4; ++i) fr[i] = frow[ty * 4 + i];
        #pragma unroll
        for (int i = 0; i < 4; ++i)
            #pragma unroll
            for (int j = 0; j < 8; ++j) acc[i][j] *= fr[i];

        #pragma unroll 4
        for (int kk = 0; kk < 32; ++kk) {
            float p[4];
            #pragma unroll
            for (int i = 0; i < 4; ++i) p[i] = Ps[(ty * 4 + i) * PPAD + kk];
            float4 v0 = *(const float4*)&Vs[kk * QPAD + tx * 8];
            float4 v1 = *(const float4*)&Vs[kk * QPAD + tx * 8 + 4];
            #pragma unroll
            for (int i = 0; i < 4; ++i) {
                acc[i][0] += p[i] * v0.x;  acc[i][1] += p[i] * v0.y;
                acc[i][2] += p[i] * v0.z;  acc[i][3] += p[i] * v0.w;
                acc[i][4] += p[i] * v1.x;  acc[i][5] += p[i] * v1.y;
                acc[i][6] += p[i] * v1.z;  acc[i][7] += p[i] * v1.w;
            }
        }
        __syncthreads();
    }

    // Epilogue: O /= l, store
    #pragma unroll
    for (int i = 0; i < 4; ++i) {
        int r = q0 + ty * 4 + i;
        if (r < SEQ) {
            float inv = 1.f / lrow[ty * 4 + i];
            #pragma unroll
            for (int j = 0; j < 8; ++j)
                O[(size_t)r * DIM + head * HD + tx * 8 + j] = acc[i][j] * inv;
        }
    }
}

// ---------------------------------------------------------------------------
extern "C" void kernel_launch(void* const* d_in, const int* in_sizes, int n_in,
                              void* d_out, int out_size)
{
    const float* x     = (const float*)d_in[0];
    const float* wq    = (const float*)d_in[1];
    const float* bq    = (const float*)d_in[2];
    const float* wk    = (const float*)d_in[3];
    const float* bk    = (const float*)d_in[4];
    const float* wv    = (const float*)d_in[5];
    const float* bv    = (const float*)d_in[6];
    const float* wo    = (const float*)d_in[7];
    const float* bo    = (const float*)d_in[8];
    const float* gq    = (const float*)d_in[9];
    const float* gk    = (const float*)d_in[10];
    const float* freqs = (const float*)d_in[11];
    const int*   seql  = (const int*)d_in[12];
    float* out = (float*)d_out;

    float *dq, *dk, *dv, *dattn;
    cudaGetSymbolAddress((void**)&dq, g_q);
    cudaGetSymbolAddress((void**)&dk, g_k);
    cudaGetSymbolAddress((void**)&dv, g_v);
    cudaGetSymbolAddress((void**)&dattn, g_attn);

    dim3 ggrid(DIM / 64, (SEQ + 63) / 64);
    gemm_bias_kernel<<<ggrid, 256>>>(x, wq, bq, dq, SEQ);
    gemm_bias_kernel<<<ggrid, 256>>>(x, wk, bk, dk, SEQ);
    gemm_bias_kernel<<<ggrid, 256>>>(x, wv, bv, dv, SEQ);

    rmsnorm_rope_kernel<<<SEQ, 256>>>(dq, gq, freqs);
    rmsnorm_rope_kernel<<<SEQ, 256>>>(dk, gk, freqs);

    const int smem_bytes = (64 * QPAD + 32 * QPAD * 2 + 64 * PPAD + 192) * sizeof(float);
    cudaFuncSetAttribute(attn_kernel, cudaFuncAttributeMaxDynamicSharedMemorySize, smem_bytes);
    dim3 agrid((SEQ + 63) / 64, NH);
    attn_kernel<<<agrid, 256, smem_bytes>>>(dq, dk, dv, seql, dattn);

    gemm_bias_kernel<<<ggrid, 256>>>(dattn, wo, bo, out, SEQ);
}

// round 12
// speedup vs baseline: 2.4889x; 2.4889x over previous
#include <cuda_runtime.h>
#include <cuda_bf16.h>
#include <math.h>
#include <cstdint>

// Problem constants
#define DIM   1536
#define NH    12
#define HD    128
#define SEQ   3744          // 3*26*48
#define GH    26
#define GW    48
#define C2    64            // HD/2
#define SP0   22
#define SP1   43
#define EPSV  1e-6f
#define SCALE 0.08838834764831843f   // HD^-0.5

// Scratch (static device arrays: allocation-free)
__device__ float g_q[SEQ * DIM];
__device__ float g_k[SEQ * DIM];
__device__ float g_v[SEQ * DIM];
__device__ float g_attn[SEQ * DIM];

// ===========================================================================
// mma.sync helpers (PTX-portable: compile for compute_103 base target)
// ===========================================================================
__device__ __forceinline__ uint32_t smem_u32(const void* p) {
    uint32_t a;
    asm("{ .reg .u64 t; cvta.to.shared.u64 t, %1; cvt.u32.u64 %0, t; }"
        : "=r"(a) : "l"(p));
    return a;
}

#define SW128(o) ((o) ^ (((o) >> 3) & 0x70u))   // 128B rows: XOR row&7 into chunk
#define SW256(o) ((o) ^ (((o) >> 4) & 0x70u))   // 256B rows: XOR row&7 into chunk

__device__ __forceinline__ void ldsm4(uint32_t* r, uint32_t a) {
    asm volatile("ldmatrix.sync.aligned.m8n8.x4.shared.b16 {%0,%1,%2,%3}, [%4];"
                 : "=r"(r[0]), "=r"(r[1]), "=r"(r[2]), "=r"(r[3]) : "r"(a));
}
__device__ __forceinline__ void ldsm4t(uint32_t* r, uint32_t a) {
    asm volatile("ldmatrix.sync.aligned.m8n8.x4.trans.shared.b16 {%0,%1,%2,%3}, [%4];"
                 : "=r"(r[0]), "=r"(r[1]), "=r"(r[2]), "=r"(r[3]) : "r"(a));
}
// D(16x8 f32) += A(16x16 bf16 row) * B(16x8 bf16 col)
__device__ __forceinline__ void mma16816(float* c, const uint32_t* a, const uint32_t* b) {
    asm volatile("mma.sync.aligned.m16n8k16.row.col.f32.bf16.bf16.f32 "
                 "{%0,%1,%2,%3}, {%4,%5,%6,%7}, {%8,%9}, {%0,%1,%2,%3};"
                 : "+f"(c[0]), "+f"(c[1]), "+f"(c[2]), "+f"(c[3])
                 : "r"(a[0]), "r"(a[1]), "r"(a[2]), "r"(a[3]),
                   "r"(b[0]), "r"(b[1]));
}

// Split two floats into packed bf16 hi and lo (residual) words
__device__ __forceinline__ void split2(float a, float b, uint32_t& hi, uint32_t& lo) {
    __nv_bfloat162 h = __floats2bfloat162_rn(a, b);
    float2 hf = __bfloat1622float2(h);
    __nv_bfloat162 l = __floats2bfloat162_rn(a - hf.x, b - hf.y);
    hi = *reinterpret_cast<uint32_t*>(&h);
    lo = *reinterpret_cast<uint32_t*>(&l);
}

__device__ __forceinline__ void ldg16(float* v, const float* s, bool ok) {
    if (ok) {
        #pragma unroll
        for (int i = 0; i < 4; ++i) *(float4*)&v[i * 4] = *(const float4*)&s[i * 4];
    } else {
        #pragma unroll
        for (int i = 0; i < 16; ++i) v[i] = 0.f;
    }
}

// Store 16 floats as split bf16 into hi/lo tiles (two 16B chunks), 128B rows
__device__ __forceinline__ void sts16_128(char* th, char* tl, const float* v, int r, int c0) {
    #pragma unroll
    for (int c = 0; c < 2; ++c) {
        uint32_t H[4], L[4];
        #pragma unroll
        for (int j = 0; j < 4; ++j)
            split2(v[c * 8 + 2 * j], v[c * 8 + 2 * j + 1], H[j], L[j]);
        uint32_t off = (uint32_t)r * 128 + (uint32_t)(c0 + c) * 16;
        uint32_t sw = SW128(off);
        *(uint4*)(th + sw) = make_uint4(H[0], H[1], H[2], H[3]);
        *(uint4*)(tl + sw) = make_uint4(L[0], L[1], L[2], L[3]);
    }
}
// Same for 256B rows
__device__ __forceinline__ void sts16_256(char* th, char* tl, const float* v, int r, int c0) {
    #pragma unroll
    for (int c = 0; c < 2; ++c) {
        uint32_t H[4], L[4];
        #pragma unroll
        for (int j = 0; j < 4; ++j)
            split2(v[c * 8 + 2 * j], v[c * 8 + 2 * j + 1], H[j], L[j]);
        uint32_t off = (uint32_t)r * 256 + (uint32_t)(c0 + c) * 16;
        uint32_t sw = SW256(off);
        *(uint4*)(th + sw) = make_uint4(H[0], H[1], H[2], H[3]);
        *(uint4*)(tl + sw) = make_uint4(L[0], L[1], L[2], L[3]);
    }
}

// ===========================================================================
// GEMM: C[M][1536] = A[M][1536] @ W[1536][1536]^T + bias  (mma.sync bf16x3)
// Tiles 128x128x64; warp grid 2(M)x4(N), warp tile 64x32; 2-stage pipeline.
// ===========================================================================
#define BM 128
#define BN 128
#define BK 64
#define NKIT (DIM / BK)          // 24
#define GA_H 0
#define GA_L 16384
#define GB_H 32768
#define GB_L 49152
#define G_STAGE 65536
#define GEMM_SMEM (2 * G_STAGE)  // 131072

__global__ __launch_bounds__(256, 1) void gemm_tc_kernel(
    const float* __restrict__ A, const float* __restrict__ W,
    const float* __restrict__ bias, float* __restrict__ C, int M)
{
    extern __shared__ char smem[];
    const uint32_t sb = smem_u32(smem);
    const int tid  = threadIdx.x;
    const int lane = tid & 31;
    const int wid  = tid >> 5;
    const int wm = wid & 1, wn = wid >> 1;
    const int row0 = blockIdx.y * BM, col0 = blockIdx.x * BN;
    const int vr = (M - row0 < BM) ? (M - row0) : BM;

    const int lr = tid >> 1;          // staging row 0..127
    const int lh = tid & 1;           // column half (32 floats)
    const float* Ab = A + (size_t)row0 * DIM + lh * 32;
    const float* Wb = W + (size_t)col0 * DIM + lh * 32;
    const bool aok = lr < vr;

    float acc[4][4][4] = {};

    float va[32], vb[32];
    // Prologue: chunk 0 -> stage 0
    {
        const float* ap = Ab + (size_t)lr * DIM;
        const float* wp = Wb + (size_t)lr * DIM;
        ldg16(va, ap, aok);  ldg16(va + 16, ap + 16, aok);
        ldg16(vb, wp, true); ldg16(vb + 16, wp + 16, true);
        sts16_128(smem + GA_H, smem + GA_L, va,      lr, lh * 4);
        sts16_128(smem + GA_H, smem + GA_L, va + 16, lr, lh * 4 + 2);
        sts16_128(smem + GB_H, smem + GB_L, vb,      lr, lh * 4);
        sts16_128(smem + GB_H, smem + GB_L, vb + 16, lr, lh * 4 + 2);
    }
    __syncthreads();

    for (int kt = 0; kt < NKIT; ++kt) {
        const bool nxt = (kt + 1 < NKIT);
        if (nxt) {
            const float* ap = Ab + (size_t)lr * DIM + (kt + 1) * BK;
            const float* wp = Wb + (size_t)lr * DIM + (kt + 1) * BK;
            ldg16(va, ap, aok);  ldg16(va + 16, ap + 16, aok);
            ldg16(vb, wp, true); ldg16(vb + 16, wp + 16, true);
        }
        const uint32_t st = sb + (uint32_t)(kt & 1) * G_STAGE;
        #pragma unroll
        for (int kb = 0; kb < 4; ++kb) {
            uint32_t ah[4][4], al[4][4];
            #pragma unroll
            for (int mt = 0; mt < 4; ++mt) {
                uint32_t r = (uint32_t)(wm * 64 + mt * 16 + (lane & 15));
                uint32_t off = r * 128 + (uint32_t)(2 * kb + (lane >> 4)) * 16;
                ldsm4(ah[mt], st + GA_H + SW128(off));
                ldsm4(al[mt], st + GA_L + SW128(off));
            }
            uint32_t bh[2][4], bl[2][4];
            #pragma unroll
            for (int ng = 0; ng < 2; ++ng) {
                uint32_t r = (uint32_t)(wn * 32 + ng * 16 + (lane & 7) + ((lane & 16) >> 1));
                uint32_t off = r * 128 + (uint32_t)(2 * kb + ((lane >> 3) & 1)) * 16;
                ldsm4(bh[ng], st + GB_H + SW128(off));
                ldsm4(bl[ng], st + GB_L + SW128(off));
            }
            #pragma unroll
            for (int mt = 0; mt < 4; ++mt)
                #pragma unroll
                for (int nt = 0; nt < 4; ++nt) {
                    const uint32_t* BH = &bh[nt >> 1][(nt & 1) * 2];
                    const uint32_t* BL = &bl[nt >> 1][(nt & 1) * 2];
                    mma16816(acc[mt][nt], ah[mt], BH);
                    mma16816(acc[mt][nt], ah[mt], BL);
                    mma16816(acc[mt][nt], al[mt], BH);
                }
        }
        if (nxt) {
            char* s2 = smem + ((kt + 1) & 1) * G_STAGE;
            sts16_128(s2 + GA_H, s2 + GA_L, va,      lr, lh * 4);
            sts16_128(s2 + GA_H, s2 + GA_L, va + 16, lr, lh * 4 + 2);
            sts16_128(s2 + GB_H, s2 + GB_L, vb,      lr, lh * 4);
            sts16_128(s2 + GB_H, s2 + GB_L, vb + 16, lr, lh * 4 + 2);
        }
        __syncthreads();
    }

    // Epilogue: registers -> gmem (+bias)
    #pragma unroll
    for (int mt = 0; mt < 4; ++mt) {
        int rl = row0 + wm * 64 + mt * 16 + (lane >> 2);
        int rh = rl + 8;
        #pragma unroll
        for (int nt = 0; nt < 4; ++nt) {
            int cc = col0 + wn * 32 + nt * 8 + (lane & 3) * 2;
            float bx = bias[cc], by = bias[cc + 1];
            if (rl < M)
                *(float2*)&C[(size_t)rl * DIM + cc] =
                    make_float2(acc[mt][nt][0] + bx, acc[mt][nt][1] + by);
            if (rh < M)
                *(float2*)&C[(size_t)rh * DIM + cc] =
                    make_float2(acc[mt][nt][2] + bx, acc[mt][nt][3] + by);
        }
    }
}

// ---------------------------------------------------------------------------
// Fused RMSNorm + gamma + RoPE, in place.
// ---------------------------------------------------------------------------
__global__ __launch_bounds__(256) void rmsnorm_rope_kernel(
    float* __restrict__ t, const float* __restrict__ g,
    const float* __restrict__ freqs)
{
    __shared__ float row[DIM];
    __shared__ float red[256];

    const int s   = blockIdx.x;
    const int tid = threadIdx.x;
    float* rp = t + (size_t)s * DIM;

    float ss = 0.f;
    for (int i = tid; i < DIM; i += 256) {
        float v = rp[i];
        row[i] = v;
        ss += v * v;
    }
    red[tid] = ss;
    __syncthreads();
    for (int o = 128; o > 0; o >>= 1) {
        if (tid < o) red[tid] += red[tid + o];
        __syncthreads();
    }
    const float scale = rsqrtf(red[0] / (float)DIM + EPSV);

    const int f   = s / (GH * GW);
    const int rem = s % (GH * GW);
    const int hh  = rem / GW;
    const int ww  = rem % GW;

    for (int p = tid; p < NH * C2; p += 256) {
        const int head = p >> 6;
        const int j    = p & 63;
        const int pos  = (j < SP0) ? f : ((j < SP1) ? hh : ww);
        const float ang = freqs[pos * C2 + j];
        float si, co;
        sincosf(ang, &si, &co);
        const int i0 = head * HD + 2 * j;
        const float xr = row[i0]     * scale * g[i0];
        const float xi = row[i0 + 1] * scale * g[i0 + 1];
        rp[i0]     = xr * co - xi * si;
        rp[i0 + 1] = xr * si + xi * co;
    }
}

// ===========================================================================
// Flash attention via mma.sync (bf16x3 for S and PV).
// CTA = 128 q x 1 head, 8 warps (warp = 16 q rows), kv tiles of 64.
// ===========================================================================
#define AQ 128
#define AK 64
#define ATILES ((SEQ + AK - 1) / AK)   // 59

#define S_QH 0               // Q hi: 128 rows x 256B
#define S_QL 32768
#define S_KH 65536           // K hi: 64 x 256B
#define S_KL 81920
#define S_VH 98304           // V hi: 64 x 256B
#define S_VL 114688
#define S_PH 131072          // P hi: 128 x 128B
#define S_PL 147456
#define ATTN_SMEM 163840

__global__ __launch_bounds__(256, 1) void attn_tc_kernel(
    const float* __restrict__ Q, const float* __restrict__ K,
    const float* __restrict__ V, const int* __restrict__ seq_lens,
    float* __restrict__ O)
{
    extern __shared__ char smem[];
    const uint32_t sb = smem_u32(smem);
    const int tid = threadIdx.x, lane = tid & 31, wid = tid >> 5;
    const int head = blockIdx.y;
    const int q0 = blockIdx.x * AQ;
    const int seqlen = seq_lens[0];

    // Load Q once (hi/lo split)
    {
        const int r  = tid >> 1;
        const int cb = (tid & 1) * 64;
        const bool ok = (q0 + r) < SEQ;
        const float* qp = Q + (size_t)(q0 + r) * DIM + head * HD + cb;
        float v[16];
        #pragma unroll
        for (int p = 0; p < 4; ++p) {
            ldg16(v, qp + p * 16, ok);
            sts16_256(smem + S_QH, smem + S_QL, v, r, (tid & 1) * 8 + p * 2);
        }
    }

    float oacc[16][4] = {};
    float m_run[2] = {-1e30f, -1e30f};
    float l_run[2] = {0.f, 0.f};

    for (int t = 0; t < ATILES; ++t) {
        const int kv0 = t * AK;
        __syncthreads();   // prev PV reads done (and Q visible on t=0)

        // Load K, V (hi/lo split)
        {
            const int r  = tid >> 2;           // kv row 0..63
            const int cb = (tid & 3) * 32;
            const bool ok = (kv0 + r) < seqlen;
            const float* kp = K + (size_t)(kv0 + r) * DIM + head * HD + cb;
            const float* vp = V + (size_t)(kv0 + r) * DIM + head * HD + cb;
            float v[16];
            #pragma unroll
            for (int p = 0; p < 2; ++p) {
                ldg16(v, kp + p * 16, ok);
                sts16_256(smem + S_KH, smem + S_KL, v, r, (tid & 3) * 4 + p * 2);
            }
            #pragma unroll
            for (int p = 0; p < 2; ++p) {
                ldg16(v, vp + p * 16, ok);
                sts16_256(smem + S_VH, smem + S_VL, v, r, (tid & 3) * 4 + p * 2);
            }
        }
        __syncthreads();

        // ---- S = Q @ K^T (bf16x3) ----
        float sacc[8][4] = {};
        #pragma unroll
        for (int kb = 0; kb < 8; ++kb) {
            uint32_t qh[4], ql[4];
            {
                uint32_t r = (uint32_t)(wid * 16 + (lane & 15));
                uint32_t off = r * 256 + (uint32_t)(2 * kb + (lane >> 4)) * 16;
                ldsm4(qh, sb + S_QH + SW256(off));
                ldsm4(ql, sb + S_QL + SW256(off));
            }
            #pragma unroll
            for (int g = 0; g < 4; ++g) {
                uint32_t r = (uint32_t)(g * 16 + (lane & 7) + ((lane & 16) >> 1));
                uint32_t off = r * 256 + (uint32_t)(2 * kb + ((lane >> 3) & 1)) * 16;
                uint32_t kh[4], kl[4];
                ldsm4(kh, sb + S_KH + SW256(off));
                ldsm4(kl, sb + S_KL + SW256(off));
                #pragma unroll
                for (int h2 = 0; h2 < 2; ++h2) {
                    float* sc = sacc[g * 2 + h2];
                    mma16816(sc, qh, &kh[h2 * 2]);
                    mma16816(sc, qh, &kl[h2 * 2]);
                    mma16816(sc, ql, &kh[h2 * 2]);
                }
            }
        }

        // ---- Online softmax (thread owns rows lane>>2 and +8 of warp tile) ----
        float mx[2] = {-1e30f, -1e30f};
        #pragma unroll
        for (int j = 0; j < 8; ++j)
            #pragma unroll
            for (int e = 0; e < 4; ++e) {
                float s = sacc[j][e] * SCALE;
                int col = j * 8 + (lane & 3) * 2 + (e & 1);
                if (kv0 + col >= seqlen) s = -1e30f;
                sacc[j][e] = s;
                mx[e >> 1] = fmaxf(mx[e >> 1], s);
            }
        #pragma unroll
        for (int i = 0; i < 2; ++i) {
            mx[i] = fmaxf(mx[i], __shfl_xor_sync(0xffffffffu, mx[i], 1));
            mx[i] = fmaxf(mx[i], __shfl_xor_sync(0xffffffffu, mx[i], 2));
        }
        float fac[2], sum[2] = {0.f, 0.f};
        #pragma unroll
        for (int i = 0; i < 2; ++i) {
            float mn = fmaxf(m_run[i], mx[i]);
            fac[i] = __expf(m_run[i] - mn);
            m_run[i] = mn;
        }
        #pragma unroll
        for (int j = 0; j < 8; ++j)
            #pragma unroll
            for (int e = 0; e < 4; ++e) {
                float p = __expf(sacc[j][e] - m_run[e >> 1]);
                sacc[j][e] = p;
                sum[e >> 1] += p;
            }
        #pragma unroll
        for (int i = 0; i < 2; ++i) {
            sum[i] += __shfl_xor_sync(0xffffffffu, sum[i], 1);
            sum[i] += __shfl_xor_sync(0xffffffffu, sum[i], 2);
            l_run[i] = l_run[i] * fac[i] + sum[i];
        }
        #pragma unroll
        for (int j = 0; j < 16; ++j) {
            oacc[j][0] *= fac[0]; oacc[j][1] *= fac[0];
            oacc[j][2] *= fac[1]; oacc[j][3] *= fac[1];
        }

        // ---- Write P (hi/lo split, 128B rows) ----
        {
            int rl = wid * 16 + (lane >> 2);
            #pragma unroll
            for (int j = 0; j < 8; ++j) {
                uint32_t H, L;
                uint32_t off = (uint32_t)rl * 128 + (uint32_t)j * 16 + (lane & 3) * 4;
                split2(sacc[j][0], sacc[j][1], H, L);
                *(uint32_t*)(smem + S_PH + SW128(off)) = H;
                *(uint32_t*)(smem + S_PL + SW128(off)) = L;
                uint32_t off2 = off + 8 * 128;
                split2(sacc[j][2], sacc[j][3], H, L);
                *(uint32_t*)(smem + S_PH + SW128(off2)) = H;
                *(uint32_t*)(smem + S_PL + SW128(off2)) = L;
            }
        }
        __syncthreads();

        // ---- O += P @ V (bf16x3; V via ldmatrix.trans) ----
        #pragma unroll
        for (int kb = 0; kb < 4; ++kb) {
            uint32_t ph[4], pl[4];
            {
                uint32_t r = (uint32_t)(wid * 16 + (lane & 15));
                uint32_t off = r * 128 + (uint32_t)(2 * kb + (lane >> 4)) * 16;
                ldsm4(ph, sb + S_PH + SW128(off));
                ldsm4(pl, sb + S_PL + SW128(off));
            }
            #pragma unroll
            for (int g = 0; g < 8; ++g) {
                uint32_t r = (uint32_t)(kb * 16 + (lane & 15));
                uint32_t off = r * 256 + (uint32_t)(2 * g + (lane >> 4)) * 16;
                uint32_t vh[4], vl[4];
                ldsm4t(vh, sb + S_VH + SW256(off));
                ldsm4t(vl, sb + S_VL + SW256(off));
                #pragma unroll
                for (int h2 = 0; h2 < 2; ++h2) {
                    float* oc = oacc[g * 2 + h2];
                    mma16816(oc, ph, &vh[h2 * 2]);
                    mma16816(oc, ph, &vl[h2 * 2]);
                    mma16816(oc, pl, &vh[h2 * 2]);
                }
            }
        }
    }

    // ---- Epilogue ----
    {
        float inv0 = 1.f / l_run[0], inv1 = 1.f / l_run[1];
        int rl = q0 + wid * 16 + (lane >> 2);
        int rh = rl + 8;
        #pragma unroll
        for (int j = 0; j < 16; ++j) {
            int d0 = j * 8 + (lane & 3) * 2;
            if (rl < SEQ)
                *(float2*)&O[(size_t)rl * DIM + head * HD + d0] =
                    make_float2(oacc[j][0] * inv0, oacc[j][1] * inv0);
            if (rh < SEQ)
                *(float2*)&O[(size_t)rh * DIM + head * HD + d0] =
                    make_float2(oacc[j][2] * inv1, oacc[j][3] * inv1);
        }
    }
}

// ---------------------------------------------------------------------------
extern "C" void kernel_launch(void* const* d_in, const int* in_sizes, int n_in,
                              void* d_out, int out_size)
{
    const float* x     = (const float*)d_in[0];
    const float* wq    = (const float*)d_in[1];
    const float* bq    = (const float*)d_in[2];
    const float* wk    = (const float*)d_in[3];
    const float* bk    = (const float*)d_in[4];
    const float* wv    = (const float*)d_in[5];
    const float* bv    = (const float*)d_in[6];
    const float* wo    = (const float*)d_in[7];
    const float* bo    = (const float*)d_in[8];
    const float* gq    = (const float*)d_in[9];
    const float* gk    = (const float*)d_in[10];
    const float* freqs = (const float*)d_in[11];
    const int*   seql  = (const int*)d_in[12];
    float* out = (float*)d_out;

    float *dq, *dk, *dv, *dattn;
    cudaGetSymbolAddress((void**)&dq, g_q);
    cudaGetSymbolAddress((void**)&dk, g_k);
    cudaGetSymbolAddress((void**)&dv, g_v);
    cudaGetSymbolAddress((void**)&dattn, g_attn);

    cudaFuncSetAttribute(gemm_tc_kernel,
                         cudaFuncAttributeMaxDynamicSharedMemorySize, GEMM_SMEM);
    cudaFuncSetAttribute(attn_tc_kernel,
                         cudaFuncAttributeMaxDynamicSharedMemorySize, ATTN_SMEM);

    dim3 ggrid(DIM / BN, (SEQ + BM - 1) / BM);   // 12 x 30
    gemm_tc_kernel<<<ggrid, 256, GEMM_SMEM>>>(x, wq, bq, dq, SEQ);
    gemm_tc_kernel<<<ggrid, 256, GEMM_SMEM>>>(x, wk, bk, dk, SEQ);
    gemm_tc_kernel<<<ggrid, 256, GEMM_SMEM>>>(x, wv, bv, dv, SEQ);

    rmsnorm_rope_kernel<<<SEQ, 256>>>(dq, gq, freqs);
    rmsnorm_rope_kernel<<<SEQ, 256>>>(dk, gk, freqs);

    dim3 agrid((SEQ + AQ - 1) / AQ, NH);         // 30 x 12
    attn_tc_kernel<<<agrid, 256, ATTN_SMEM>>>(dq, dk, dv, seql, dattn);

    gemm_tc_kernel<<<ggrid, 256, GEMM_SMEM>>>(dattn, wo, bo, out, SEQ);
}

// round 14
// speedup vs baseline: 3.1824x; 1.2786x over previous
#include <cuda_runtime.h>
#include <cuda_bf16.h>
#include <math.h>
#include <cstdint>

// Problem constants
#define DIM   1536
#define NH    12
#define HD    128
#define SEQ   3744          // 3*26*48
#define GH    26
#define GW    48
#define C2    64            // HD/2
#define SP0   22
#define SP1   43
#define EPSV  1e-6f
#define SCALE 0.08838834764831843f   // HD^-0.5

// Scratch (static device arrays: allocation-free)
__device__ float g_q[SEQ * DIM];
__device__ float g_k[SEQ * DIM];
__device__ float g_v[SEQ * DIM];

__device__ __nv_bfloat16 g_xh[SEQ * DIM],  g_xl[SEQ * DIM];
__device__ __nv_bfloat16 g_wqh[DIM * DIM], g_wql[DIM * DIM];
__device__ __nv_bfloat16 g_wkh[DIM * DIM], g_wkl[DIM * DIM];
__device__ __nv_bfloat16 g_wvh[DIM * DIM], g_wvl[DIM * DIM];
__device__ __nv_bfloat16 g_woh[DIM * DIM], g_wol[DIM * DIM];
__device__ __nv_bfloat16 g_qh[SEQ * DIM],  g_ql[SEQ * DIM];
__device__ __nv_bfloat16 g_kh[SEQ * DIM],  g_kl[SEQ * DIM];
__device__ __nv_bfloat16 g_vh[SEQ * DIM],  g_vl[SEQ * DIM];
__device__ __nv_bfloat16 g_ath[SEQ * DIM], g_atl[SEQ * DIM];

// ===========================================================================
// Helpers
// ===========================================================================
__device__ __forceinline__ uint32_t smem_u32(const void* p) {
    uint32_t a;
    asm("{ .reg .u64 t; cvta.to.shared.u64 t, %1; cvt.u32.u64 %0, t; }"
        : "=r"(a) : "l"(p));
    return a;
}

#define SW128(o) ((o) ^ (((o) >> 3) & 0x70u))
#define SW256(o) ((o) ^ (((o) >> 4) & 0x70u))

__device__ __forceinline__ void ldsm4(uint32_t* r, uint32_t a) {
    asm volatile("ldmatrix.sync.aligned.m8n8.x4.shared.b16 {%0,%1,%2,%3}, [%4];"
                 : "=r"(r[0]), "=r"(r[1]), "=r"(r[2]), "=r"(r[3]) : "r"(a));
}
__device__ __forceinline__ void ldsm4t(uint32_t* r, uint32_t a) {
    asm volatile("ldmatrix.sync.aligned.m8n8.x4.trans.shared.b16 {%0,%1,%2,%3}, [%4];"
                 : "=r"(r[0]), "=r"(r[1]), "=r"(r[2]), "=r"(r[3]) : "r"(a));
}
__device__ __forceinline__ void mma16816(float* c, const uint32_t* a, const uint32_t* b) {
    asm volatile("mma.sync.aligned.m16n8k16.row.col.f32.bf16.bf16.f32 "
                 "{%0,%1,%2,%3}, {%4,%5,%6,%7}, {%8,%9}, {%0,%1,%2,%3};"
                 : "+f"(c[0]), "+f"(c[1]), "+f"(c[2]), "+f"(c[3])
                 : "r"(a[0]), "r"(a[1]), "r"(a[2]), "r"(a[3]),
                   "r"(b[0]), "r"(b[1]));
}

__device__ __forceinline__ void split2(float a, float b, uint32_t& hi, uint32_t& lo) {
    __nv_bfloat162 h = __floats2bfloat162_rn(a, b);
    float2 hf = __bfloat1622float2(h);
    __nv_bfloat162 l = __floats2bfloat162_rn(a - hf.x, b - hf.y);
    hi = *reinterpret_cast<uint32_t*>(&h);
    lo = *reinterpret_cast<uint32_t*>(&l);
}

__device__ __forceinline__ void cpa16(uint32_t dst, const void* src, bool ok) {
    int sz = ok ? 16 : 0;
    asm volatile("cp.async.cg.shared.global [%0], [%1], 16, %2;"
                 :: "r"(dst), "l"(src), "r"(sz) : "memory");
}
#define CP_COMMIT() asm volatile("cp.async.commit_group;" ::: "memory")
#define CP_WAIT0()  asm volatile("cp.async.wait_group 0;" ::: "memory")

// ===========================================================================
// Pre-split fp32 -> bf16 hi/lo
// ===========================================================================
__global__ __launch_bounds__(256) void convert_split_kernel(
    const float* __restrict__ src, __nv_bfloat16* __restrict__ hi,
    __nv_bfloat16* __restrict__ lo, int n)
{
    int i = (blockIdx.x * blockDim.x + threadIdx.x) * 4;
    if (i >= n) return;
    float4 v = *(const float4*)&src[i];
    uint32_t h0, l0, h1, l1;
    split2(v.x, v.y, h0, l0);
    split2(v.z, v.w, h1, l1);
    *(uint2*)&hi[i] = make_uint2(h0, h1);
    *(uint2*)&lo[i] = make_uint2(l0, l1);
}

// ===========================================================================
// GEMM: C[M][1536] = A[M][1536] @ W[1536][1536]^T + bias (mma.sync bf16x3)
// Inputs pre-split to bf16 hi/lo. cp.async double-buffered pipeline.
// ===========================================================================
#define BM 128
#define BN 128
#define BK 64
#define NKIT (DIM / BK)          // 24
#define GA_H 0
#define GA_L 16384
#define GB_H 32768
#define GB_L 49152
#define G_STAGE 65536
#define GEMM_SMEM (2 * G_STAGE)  // 131072

__global__ __launch_bounds__(256, 1) void gemm_tc_kernel(
    const __nv_bfloat16* __restrict__ Ah, const __nv_bfloat16* __restrict__ Al,
    const __nv_bfloat16* __restrict__ Wh, const __nv_bfloat16* __restrict__ Wl,
    const float* __restrict__ bias, float* __restrict__ C, int M)
{
    extern __shared__ char smem[];
    const uint32_t sb = smem_u32(smem);
    const int tid  = threadIdx.x;
    const int lane = tid & 31;
    const int wid  = tid >> 5;
    const int wm = wid & 1, wn = wid >> 1;
    const int row0 = blockIdx.y * BM, col0 = blockIdx.x * BN;

    const int lr = tid >> 1;
    const int lh = tid & 1;
    const bool aok = (row0 + lr) < M;
    const size_t arow = (size_t)(row0 + lr) * DIM + lh * 32;
    const size_t wrow = (size_t)(col0 + lr) * DIM + lh * 32;

    // Prologue: chunk 0 -> stage 0
    #pragma unroll
    for (int i = 0; i < 4; ++i) {
        uint32_t off = SW128((uint32_t)lr * 128 + (uint32_t)(lh * 4 + i) * 16);
        cpa16(sb + GA_H + off, Ah + arow + i * 8, aok);
        cpa16(sb + GA_L + off, Al + arow + i * 8, aok);
        cpa16(sb + GB_H + off, Wh + wrow + i * 8, true);
        cpa16(sb + GB_L + off, Wl + wrow + i * 8, true);
    }
    CP_COMMIT();

    float acc[4][4][4] = {};

    for (int kt = 0; kt < NKIT; ++kt) {
        CP_WAIT0();
        __syncthreads();

        if (kt + 1 < NKIT) {
            const uint32_t s2 = sb + (uint32_t)((kt + 1) & 1) * G_STAGE;
            const size_t ko = (size_t)(kt + 1) * BK;
            #pragma unroll
            for (int i = 0; i < 4; ++i) {
                uint32_t off = SW128((uint32_t)lr * 128 + (uint32_t)(lh * 4 + i) * 16);
                cpa16(s2 + GA_H + off, Ah + arow + ko + i * 8, aok);
                cpa16(s2 + GA_L + off, Al + arow + ko + i * 8, aok);
                cpa16(s2 + GB_H + off, Wh + wrow + ko + i * 8, true);
                cpa16(s2 + GB_L + off, Wl + wrow + ko + i * 8, true);
            }
            CP_COMMIT();
        }

        const uint32_t st = sb + (uint32_t)(kt & 1) * G_STAGE;
        #pragma unroll
        for (int kb = 0; kb < 4; ++kb) {
            uint32_t ah[4][4], al[4][4];
            #pragma unroll
            for (int mt = 0; mt < 4; ++mt) {
                uint32_t r = (uint32_t)(wm * 64 + mt * 16 + (lane & 15));
                uint32_t off = r * 128 + (uint32_t)(2 * kb + (lane >> 4)) * 16;
                ldsm4(ah[mt], st + GA_H + SW128(off));
                ldsm4(al[mt], st + GA_L + SW128(off));
            }
            uint32_t bh[2][4], bl[2][4];
            #pragma unroll
            for (int ng = 0; ng < 2; ++ng) {
                uint32_t r = (uint32_t)(wn * 32 + ng * 16 + (lane & 7) + ((lane & 16) >> 1));
                uint32_t off = r * 128 + (uint32_t)(2 * kb + ((lane >> 3) & 1)) * 16;
                ldsm4(bh[ng], st + GB_H + SW128(off));
                ldsm4(bl[ng], st + GB_L + SW128(off));
            }
            #pragma unroll
            for (int mt = 0; mt < 4; ++mt)
                #pragma unroll
                for (int nt = 0; nt < 4; ++nt) {
                    const uint32_t* BH = &bh[nt >> 1][(nt & 1) * 2];
                    const uint32_t* BL = &bl[nt >> 1][(nt & 1) * 2];
                    mma16816(acc[mt][nt], ah[mt], BH);
                    mma16816(acc[mt][nt], ah[mt], BL);
                    mma16816(acc[mt][nt], al[mt], BH);
                }
        }
    }

    // Epilogue: registers -> gmem (+bias)
    #pragma unroll
    for (int mt = 0; mt < 4; ++mt) {
        int rl = row0 + wm * 64 + mt * 16 + (lane >> 2);
        int rh = rl + 8;
        #pragma unroll
        for (int nt = 0; nt < 4; ++nt) {
            int cc = col0 + wn * 32 + nt * 8 + (lane & 3) * 2;
            float bx = bias[cc], by = bias[cc + 1];
            if (rl < M)
                *(float2*)&C[(size_t)rl * DIM + cc] =
                    make_float2(acc[mt][nt][0] + bx, acc[mt][nt][1] + by);
            if (rh < M)
                *(float2*)&C[(size_t)rh * DIM + cc] =
                    make_float2(acc[mt][nt][2] + bx, acc[mt][nt][3] + by);
        }
    }
}

// ---------------------------------------------------------------------------
// Fused RMSNorm + gamma + RoPE; fp32 in, bf16 hi/lo out.
// ---------------------------------------------------------------------------
__global__ __launch_bounds__(256) void rmsnorm_rope_kernel(
    const float* __restrict__ t, __nv_bfloat16* __restrict__ oh,
    __nv_bfloat16* __restrict__ ol, const float* __restrict__ g,
    const float* __restrict__ freqs)
{
    __shared__ float row[DIM];
    __shared__ float red[256];

    const int s   = blockIdx.x;
    const int tid = threadIdx.x;
    const float* rp = t + (size_t)s * DIM;

    float ss = 0.f;
    for (int i = tid; i < DIM; i += 256) {
        float v = rp[i];
        row[i] = v;
        ss += v * v;
    }
    red[tid] = ss;
    __syncthreads();
    for (int o = 128; o > 0; o >>= 1) {
        if (tid < o) red[tid] += red[tid + o];
        __syncthreads();
    }
    const float scale = rsqrtf(red[0] / (float)DIM + EPSV);

    const int f   = s / (GH * GW);
    const int rem = s % (GH * GW);
    const int hh  = rem / GW;
    const int ww  = rem % GW;

    for (int p = tid; p < NH * C2; p += 256) {
        const int head = p >> 6;
        const int j    = p & 63;
        const int pos  = (j < SP0) ? f : ((j < SP1) ? hh : ww);
        const float ang = freqs[pos * C2 + j];
        float si, co;
        sincosf(ang, &si, &co);
        const int i0 = head * HD + 2 * j;
        const float xr = row[i0]     * scale * g[i0];
        const float xi = row[i0 + 1] * scale * g[i0 + 1];
        const float yr = xr * co - xi * si;
        const float yi = xr * si + xi * co;
        uint32_t H, L;
        split2(yr, yi, H, L);
        *(uint32_t*)&oh[(size_t)s * DIM + i0] = H;
        *(uint32_t*)&ol[(size_t)s * DIM + i0] = L;
    }
}

// ===========================================================================
// Flash attention via mma.sync (bf16x3 for S and PV), bf16 hi/lo inputs.
// CTA = 128 q x 1 head, 8 warps (warp = 16 q rows), kv tiles of 64.
// ===========================================================================
#define AQ 128
#define AK 64
#define ATILES ((SEQ + AK - 1) / AK)   // 59

#define S_QH 0               // Q hi: 128 rows x 256B
#define S_QL 32768
#define S_KH 65536           // K hi: 64 x 256B
#define S_KL 81920
#define S_VH 98304           // V hi: 64 x 256B
#define S_VL 114688
#define S_PH 131072          // P hi: 128 x 128B
#define S_PL 147456
#define ATTN_SMEM 163840

__global__ __launch_bounds__(256, 1) void attn_tc_kernel(
    const __nv_bfloat16* __restrict__ Qh, const __nv_bfloat16* __restrict__ Ql,
    const __nv_bfloat16* __restrict__ Kh, const __nv_bfloat16* __restrict__ Kl,
    const __nv_bfloat16* __restrict__ Vh, const __nv_bfloat16* __restrict__ Vl,
    const int* __restrict__ seq_lens,
    __nv_bfloat16* __restrict__ Oh, __nv_bfloat16* __restrict__ Ol)
{
    extern __shared__ char smem[];
    const uint32_t sb = smem_u32(smem);
    const int tid = threadIdx.x, lane = tid & 31, wid = tid >> 5;
    const int head = blockIdx.y;
    const int q0 = blockIdx.x * AQ;
    const int seqlen = seq_lens[0];

    // Load Q once (bf16 hi/lo, cp.async)
    {
        const int r = tid >> 1, half = tid & 1;
        const bool ok = (q0 + r) < SEQ;
        const size_t base = (size_t)(q0 + r) * DIM + head * HD + half * 64;
        #pragma unroll
        for (int i = 0; i < 8; ++i) {
            uint32_t off = SW256((uint32_t)r * 256 + (uint32_t)(half * 8 + i) * 16);
            cpa16(sb + S_QH + off, Qh + base + i * 8, ok);
            cpa16(sb + S_QL + off, Ql + base + i * 8, ok);
        }
        CP_COMMIT();
    }

    float oacc[16][4] = {};
    float m_run[2] = {-1e30f, -1e30f};
    float l_run[2] = {0.f, 0.f};

    for (int t = 0; t < ATILES; ++t) {
        const int kv0 = t * AK;
        __syncthreads();   // prev PV reads done

        // Load K, V (bf16 hi/lo, cp.async)
        {
            const int r = tid >> 2, q4 = tid & 3;
            const bool ok = (kv0 + r) < seqlen;
            const size_t base = (size_t)(kv0 + r) * DIM + head * HD + q4 * 32;
            #pragma unroll
            for (int i = 0; i < 4; ++i) {
                uint32_t off = SW256((uint32_t)r * 256 + (uint32_t)(q4 * 4 + i) * 16);
                cpa16(sb + S_KH + off, Kh + base + i * 8, ok);
                cpa16(sb + S_KL + off, Kl + base + i * 8, ok);
                cpa16(sb + S_VH + off, Vh + base + i * 8, ok);
                cpa16(sb + S_VL + off, Vl + base + i * 8, ok);
            }
            CP_COMMIT();
        }
        CP_WAIT0();
        __syncthreads();

        // ---- S = Q @ K^T (bf16x3) ----
        float sacc[8][4] = {};
        #pragma unroll
        for (int kb = 0; kb < 8; ++kb) {
            uint32_t qh[4], ql[4];
            {
                uint32_t r = (uint32_t)(wid * 16 + (lane & 15));
                uint32_t off = r * 256 + (uint32_t)(2 * kb + (lane >> 4)) * 16;
                ldsm4(qh, sb + S_QH + SW256(off));
                ldsm4(ql, sb + S_QL + SW256(off));
            }
            #pragma unroll
            for (int g = 0; g < 4; ++g) {
                uint32_t r = (uint32_t)(g * 16 + (lane & 7) + ((lane & 16) >> 1));
                uint32_t off = r * 256 + (uint32_t)(2 * kb + ((lane >> 3) & 1)) * 16;
                uint32_t kh[4], kl[4];
                ldsm4(kh, sb + S_KH + SW256(off));
                ldsm4(kl, sb + S_KL + SW256(off));
                #pragma unroll
                for (int h2 = 0; h2 < 2; ++h2) {
                    float* sc = sacc[g * 2 + h2];
                    mma16816(sc, qh, &kh[h2 * 2]);
                    mma16816(sc, qh, &kl[h2 * 2]);
                    mma16816(sc, ql, &kh[h2 * 2]);
                }
            }
        }

        // ---- Online softmax ----
        float mx[2] = {-1e30f, -1e30f};
        #pragma unroll
        for (int j = 0; j < 8; ++j)
            #pragma unroll
            for (int e = 0; e < 4; ++e) {
                float s = sacc[j][e] * SCALE;
                int col = j * 8 + (lane & 3) * 2 + (e & 1);
                if (kv0 + col >= seqlen) s = -1e30f;
                sacc[j][e] = s;
                mx[e >> 1] = fmaxf(mx[e >> 1], s);
            }
        #pragma unroll
        for (int i = 0; i < 2; ++i) {
            mx[i] = fmaxf(mx[i], __shfl_xor_sync(0xffffffffu, mx[i], 1));
            mx[i] = fmaxf(mx[i], __shfl_xor_sync(0xffffffffu, mx[i], 2));
        }
        float fac[2], sum[2] = {0.f, 0.f};
        #pragma unroll
        for (int i = 0; i < 2; ++i) {
            float mn = fmaxf(m_run[i], mx[i]);
            fac[i] = __expf(m_run[i] - mn);
            m_run[i] = mn;
        }
        #pragma unroll
        for (int j = 0; j < 8; ++j)
            #pragma unroll
            for (int e = 0; e < 4; ++e) {
                float p = __expf(sacc[j][e] - m_run[e >> 1]);
                sacc[j][e] = p;
                sum[e >> 1] += p;
            }
        #pragma unroll
        for (int i = 0; i < 2; ++i) {
            sum[i] += __shfl_xor_sync(0xffffffffu, sum[i], 1);
            sum[i] += __shfl_xor_sync(0xffffffffu, sum[i], 2);
            l_run[i] = l_run[i] * fac[i] + sum[i];
        }
        #pragma unroll
        for (int j = 0; j < 16; ++j) {
            oacc[j][0] *= fac[0]; oacc[j][1] *= fac[0];
            oacc[j][2] *= fac[1]; oacc[j][3] *= fac[1];
        }

        // ---- Write P (hi/lo split, 128B rows) ----
        {
            int rl = wid * 16 + (lane >> 2);
            #pragma unroll
            for (int j = 0; j < 8; ++j) {
                uint32_t H, L;
                uint32_t off = (uint32_t)rl * 128 + (uint32_t)j * 16 + (lane & 3) * 4;
                split2(sacc[j][0], sacc[j][1], H, L);
                *(uint32_t*)(smem + S_PH + SW128(off)) = H;
                *(uint32_t*)(smem + S_PL + SW128(off)) = L;
                uint32_t off2 = off + 8 * 128;
                split2(sacc[j][2], sacc[j][3], H, L);
                *(uint32_t*)(smem + S_PH + SW128(off2)) = H;
                *(uint32_t*)(smem + S_PL + SW128(off2)) = L;
            }
        }
        __syncthreads();

        // ---- O += P @ V (bf16x3; V via ldmatrix.trans) ----
        #pragma unroll
        for (int kb = 0; kb < 4; ++kb) {
            uint32_t ph[4], pl[4];
            {
                uint32_t r = (uint32_t)(wid * 16 + (lane & 15));
                uint32_t off = r * 128 + (uint32_t)(2 * kb + (lane >> 4)) * 16;
                ldsm4(ph, sb + S_PH + SW128(off));
                ldsm4(pl, sb + S_PL + SW128(off));
            }
            #pragma unroll
            for (int g = 0; g < 8; ++g) {
                uint32_t r = (uint32_t)(kb * 16 + (lane & 15));
                uint32_t off = r * 256 + (uint32_t)(2 * g + (lane >> 4)) * 16;
                uint32_t vh[4], vl[4];
                ldsm4t(vh, sb + S_VH + SW256(off));
                ldsm4t(vl, sb + S_VL + SW256(off));
                #pragma unroll
                for (int h2 = 0; h2 < 2; ++h2) {
                    float* oc = oacc[g * 2 + h2];
                    mma16816(oc, ph, &vh[h2 * 2]);
                    mma16816(oc, ph, &vl[h2 * 2]);
                    mma16816(oc, pl, &vh[h2 * 2]);
                }
            }
        }
    }

    // ---- Epilogue: O /= l, write hi/lo bf16 ----
    {
        float inv0 = 1.f / l_run[0], inv1 = 1.f / l_run[1];
        int rl = q0 + wid * 16 + (lane >> 2);
        int rh = rl + 8;
        #pragma unroll
        for (int j = 0; j < 16; ++j) {
            int d0 = j * 8 + (lane & 3) * 2;
            uint32_t H, L;
            if (rl < SEQ) {
                split2(oacc[j][0] * inv0, oacc[j][1] * inv0, H, L);
                *(uint32_t*)&Oh[(size_t)rl * DIM + head * HD + d0] = H;
                *(uint32_t*)&Ol[(size_t)rl * DIM + head * HD + d0] = L;
            }
            if (rh < SEQ) {
                split2(oacc[j][2] * inv1, oacc[j][3] * inv1, H, L);
                *(uint32_t*)&Oh[(size_t)rh * DIM + head * HD + d0] = H;
                *(uint32_t*)&Ol[(size_t)rh * DIM + head * HD + d0] = L;
            }
        }
    }
}

// ---------------------------------------------------------------------------
extern "C" void kernel_launch(void* const* d_in, const int* in_sizes, int n_in,
                              void* d_out, int out_size)
{
    const float* x     = (const float*)d_in[0];
    const float* wq    = (const float*)d_in[1];
    const float* bq    = (const float*)d_in[2];
    const float* wk    = (const float*)d_in[3];
    const float* bk    = (const float*)d_in[4];
    const float* wv    = (const float*)d_in[5];
    const float* bv    = (const float*)d_in[6];
    const float* wo    = (const float*)d_in[7];
    const float* bo    = (const float*)d_in[8];
    const float* gq    = (const float*)d_in[9];
    const float* gk    = (const float*)d_in[10];
    const float* freqs = (const float*)d_in[11];
    const int*   seql  = (const int*)d_in[12];
    float* out = (float*)d_out;

    float *dq, *dk, *dv;
    __nv_bfloat16 *xh, *xl, *wqh, *wql, *wkh, *wkl, *wvh, *wvl, *woh, *wol;
    __nv_bfloat16 *qh, *ql, *kh, *kl, *vh, *vl, *ath, *atl;
    cudaGetSymbolAddress((void**)&dq, g_q);
    cudaGetSymbolAddress((void**)&dk, g_k);
    cudaGetSymbolAddress((void**)&dv, g_v);
    cudaGetSymbolAddress((void**)&xh, g_xh);   cudaGetSymbolAddress((void**)&xl, g_xl);
    cudaGetSymbolAddress((void**)&wqh, g_wqh); cudaGetSymbolAddress((void**)&wql, g_wql);
    cudaGetSymbolAddress((void**)&wkh, g_wkh); cudaGetSymbolAddress((void**)&wkl, g_wkl);
    cudaGetSymbolAddress((void**)&wvh, g_wvh); cudaGetSymbolAddress((void**)&wvl, g_wvl);
    cudaGetSymbolAddress((void**)&woh, g_woh); cudaGetSymbolAddress((void**)&wol, g_wol);
    cudaGetSymbolAddress((void**)&qh, g_qh);   cudaGetSymbolAddress((void**)&ql, g_ql);
    cudaGetSymbolAddress((void**)&kh, g_kh);   cudaGetSymbolAddress((void**)&kl, g_kl);
    cudaGetSymbolAddress((void**)&vh, g_vh);   cudaGetSymbolAddress((void**)&vl, g_vl);
    cudaGetSymbolAddress((void**)&ath, g_ath); cudaGetSymbolAddress((void**)&atl, g_atl);

    cudaFuncSetAttribute(gemm_tc_kernel,
                         cudaFuncAttributeMaxDynamicSharedMemorySize, GEMM_SMEM);
    cudaFuncSetAttribute(attn_tc_kernel,
                         cudaFuncAttributeMaxDynamicSharedMemorySize, ATTN_SMEM);

    const int nx = SEQ * DIM, nw = DIM * DIM;
    convert_split_kernel<<<(nx / 4 + 255) / 256, 256>>>(x, xh, xl, nx);
    convert_split_kernel<<<(nw / 4 + 255) / 256, 256>>>(wq, wqh, wql, nw);
    convert_split_kernel<<<(nw / 4 + 255) / 256, 256>>>(wk, wkh, wkl, nw);
    convert_split_kernel<<<(nw / 4 + 255) / 256, 256>>>(wv, wvh, wvl, nw);
    convert_split_kernel<<<(nw / 4 + 255) / 256, 256>>>(wo, woh, wol, nw);

    dim3 ggrid(DIM / BN, (SEQ + BM - 1) / BM);   // 12 x 30
    gemm_tc_kernel<<<ggrid, 256, GEMM_SMEM>>>(xh, xl, wqh, wql, bq, dq, SEQ);
    gemm_tc_kernel<<<ggrid, 256, GEMM_SMEM>>>(xh, xl, wkh, wkl, bk, dk, SEQ);
    gemm_tc_kernel<<<ggrid, 256, GEMM_SMEM>>>(xh, xl, wvh, wvl, bv, dv, SEQ);

    rmsnorm_rope_kernel<<<SEQ, 256>>>(dq, qh, ql, gq, freqs);
    rmsnorm_rope_kernel<<<SEQ, 256>>>(dk, kh, kl, gk, freqs);
    convert_split_kernel<<<(nx / 4 + 255) / 256, 256>>>(dv, vh, vl, nx);

    dim3 agrid((SEQ + AQ - 1) / AQ, NH);         // 30 x 12
    attn_tc_kernel<<<agrid, 256, ATTN_SMEM>>>(qh, ql, kh, kl, vh, vl, seql, ath, atl);

    gemm_tc_kernel<<<ggrid, 256, GEMM_SMEM>>>(ath, atl, woh, wol, bo, out, SEQ);
}